// round 16
// baseline (speedup 1.0000x reference)
#include <cuda_runtime.h>
#include <cstdint>
#include <cstddef>

#define BB 32
#define NN 512
#define CC 768
#define HH 12
#define HD 64
#define MTOT (BB*NN)      // 16384
#define NC3 (3*CC)        // 2304

typedef signed char s8;

// ---------------- device scratch (allocation-free) ----------------
__device__ float g_sc[8]; // 0:a_in 1:qa 2:ka 3:va 4:aa 5:pa 6:cs1 7:apx
__device__ s8    g_xq[MTOT*CC];
__device__ s8    g_wq[NC3*CC];
__device__ float g_bi[NC3];
__device__ s8    g_q2[BB*HH*NN*HD];
__device__ s8    g_k2[BB*HH*NN*HD];
__device__ s8    g_v2t[BB*HH*HD*NN];   // [bh][d][n]
__device__ s8    g_x1[MTOT*CC];
__device__ s8    g_pw[CC*CC];

__device__ __forceinline__ float warp_sum(float v){
#pragma unroll
    for (int o = 16; o > 0; o >>= 1)
        v = __fadd_rn(v, __shfl_xor_sync(0xffffffffu, v, o));
    return v;
}

__device__ __forceinline__ s8 q_rc(float v, float a, float lo, float hi){
    float r = __fdiv_rn(v, a);
    r = fminf(fmaxf(r, lo), hi);
    return (s8)(int)rintf(r);
}

// exact 2^ei for integer ei >= -126
__device__ __forceinline__ float p2i(int ei){
    int ec = max(ei, -126);
    return __int_as_float((ec + 127) << 23);
}

__device__ __forceinline__ void mma_s8(int* d, const int* a, const int* b){
    asm volatile(
        "mma.sync.aligned.m16n8k32.row.col.s32.s8.s8.s32 "
        "{%0,%1,%2,%3}, {%4,%5,%6,%7}, {%8,%9}, {%0,%1,%2,%3};"
        : "+r"(d[0]), "+r"(d[1]), "+r"(d[2]), "+r"(d[3])
        : "r"(a[0]), "r"(a[1]), "r"(a[2]), "r"(a[3]), "r"(b[0]), "r"(b[1]));
}

__device__ __forceinline__ uint32_t smem_u32(const void* p){
    uint32_t a;
    asm("{ .reg .u64 t; cvta.to.shared.u64 t, %1; cvt.u32.u64 %0, t; }" : "=r"(a) : "l"(p));
    return a;
}
__device__ __forceinline__ void cpa16(uint32_t dst, const void* src){
    asm volatile("cp.async.ca.shared.global [%0], [%1], 16;" :: "r"(dst), "l"(src));
}
#define CPA_COMMIT() asm volatile("cp.async.commit_group;" ::: "memory")
#define CPA_WAIT(n)  asm volatile("cp.async.wait_group %0;" :: "n"(n) : "memory")

// ---------------- scalar means + integer bias ----------------
__global__ void k_scalars(const float* __restrict__ qaa, const float* __restrict__ qact,
                          const float* __restrict__ kact, const float* __restrict__ vact,
                          const float* __restrict__ aact, const float* __restrict__ paa,
                          const float* __restrict__ qkv_bias, const float* __restrict__ qkv_alpha){
    int tid = threadIdx.x;
    if (tid < 32){
        int lane = tid;
        float s = 0.f;
        for (int i = lane; i < 768; i += 32) s = __fadd_rn(s, qaa[i]);
        float a_in = __fdiv_rn(warp_sum(s), 768.0f);
        s = 0.f;
        for (int i = lane; i < 768; i += 32) s = __fadd_rn(s, paa[i]);
        float pa = __fdiv_rn(warp_sum(s), 768.0f);
        float t;
        t = (lane < 12) ? qact[lane] : 0.f; float qa = __fdiv_rn(warp_sum(t), 12.0f);
        t = (lane < 12) ? kact[lane] : 0.f; float ka = __fdiv_rn(warp_sum(t), 12.0f);
        t = (lane < 12) ? vact[lane] : 0.f; float va = __fdiv_rn(warp_sum(t), 12.0f);
        t = (lane < 12) ? aact[lane] : 0.f; float aa = __fdiv_rn(warp_sum(t), 12.0f);
        if (lane == 0){
            g_sc[0] = a_in; g_sc[1] = qa; g_sc[2] = ka; g_sc[3] = va; g_sc[4] = aa; g_sc[5] = pa;
            float sm = __fmul_rn(__fmul_rn(0.125f, qa), ka);
            g_sc[6] = __fmul_rn(1.4426950408889634f, sm);
            g_sc[7] = __fdiv_rn(pa, __fmul_rn(aa, va));
        }
    }
    __syncthreads();
    float a_in = g_sc[0];
    for (int j = tid; j < NC3; j += 256)
        g_bi[j] = truncf(__fdiv_rn(__fdiv_rn(qkv_bias[j], a_in), qkv_alpha[j]));
}

// ---------------- fused input+weight quantization ----------------
__global__ void k_quant_xw(const float* __restrict__ x, const float* __restrict__ w,
                           const float* __restrict__ al){
    if (blockIdx.x < 3072){
        float a = g_sc[0];
        int base = blockIdx.x * 1024 + threadIdx.x;
        float4 v[4];
#pragma unroll
        for (int p = 0; p < 4; p++) v[p] = ((const float4*)x)[base + p * 256];
#pragma unroll
        for (int p = 0; p < 4; p++){
            char4 c;
            c.x = q_rc(v[p].x, a, -8.f, 7.f); c.y = q_rc(v[p].y, a, -8.f, 7.f);
            c.z = q_rc(v[p].z, a, -8.f, 7.f); c.w = q_rc(v[p].w, a, -8.f, 7.f);
            ((char4*)g_xq)[base + p * 256] = c;
        }
    } else {
        int idx = (blockIdx.x - 3072) * 256 + threadIdx.x;
        int row = idx / 192;
        float a = al[row];
        float4 v = ((const float4*)w)[idx];
        char4 c;
        c.x = q_rc(v.x, a, -8.f, 7.f); c.y = q_rc(v.y, a, -8.f, 7.f);
        c.z = q_rc(v.z, a, -8.f, 7.f); c.w = q_rc(v.w, a, -8.f, 7.f);
        ((char4*)g_wq)[idx] = c;
    }
}

__global__ void k_quant_pw(const float* __restrict__ w, const float* __restrict__ al){
    int idx = blockIdx.x * 256 + threadIdx.x;
    int row = idx / 192;
    float a = al[row];
    float4 v = ((const float4*)w)[idx];
    char4 c;
    c.x = q_rc(v.x, a, -8.f, 7.f); c.y = q_rc(v.y, a, -8.f, 7.f);
    c.z = q_rc(v.z, a, -8.f, 7.f); c.w = q_rc(v.w, a, -8.f, 7.f);
    ((char4*)g_pw)[idx] = c;
}

// ---------------- GEMM compute tile (shared by gemm1/gemm2) ----------------
__device__ __forceinline__ void gemm_stage_compute(
        const s8* Atile, const s8* Btile, int lane, int wrBase, int wcBase,
        int acc[4][4][4]){
#pragma unroll
    for (int s = 0; s < 4; s++){
        int c4 = (lane & 3) * 4;
        int afr[4][4];
#pragma unroll
        for (int mt = 0; mt < 4; mt++){
            int r0 = wrBase + mt * 16 + (lane >> 2);
            int r1 = r0 + 8;
            afr[mt][0] = *(const int*)(Atile + r0*128 + (((2*s  ) ^ (r0 & 7)) * 16) + c4);
            afr[mt][1] = *(const int*)(Atile + r1*128 + (((2*s  ) ^ (r1 & 7)) * 16) + c4);
            afr[mt][2] = *(const int*)(Atile + r0*128 + (((2*s+1) ^ (r0 & 7)) * 16) + c4);
            afr[mt][3] = *(const int*)(Atile + r1*128 + (((2*s+1) ^ (r1 & 7)) * 16) + c4);
        }
        int bfr[4][2];
#pragma unroll
        for (int nt = 0; nt < 4; nt++){
            int c0 = wcBase + nt * 8 + (lane >> 2);
            bfr[nt][0] = *(const int*)(Btile + c0*128 + (((2*s  ) ^ (c0 & 7)) * 16) + c4);
            bfr[nt][1] = *(const int*)(Btile + c0*128 + (((2*s+1) ^ (c0 & 7)) * 16) + c4);
        }
#pragma unroll
        for (int mt = 0; mt < 4; mt++)
#pragma unroll
            for (int nt = 0; nt < 4; nt++)
                mma_s8(acc[mt][nt], afr[mt], bfr[nt]);
    }
}

__device__ __forceinline__ void gemm_stage_load(
        uint32_t smb, int stage, int tid,
        const s8* __restrict__ Ag, const s8* __restrict__ Bg, int kt){
    uint32_t sA = smb + stage * 32768;
    uint32_t sB = sA + 16384;
#pragma unroll
    for (int p = 0; p < 4; p++){
        int idx = tid + p * 256;
        int r = idx >> 3, seg = idx & 7;
        uint32_t off = r * 128 + ((seg ^ (r & 7)) * 16);
        cpa16(sA + off, Ag + (size_t)r * 768 + kt + seg * 16);
        cpa16(sB + off, Bg + (size_t)r * 768 + kt + seg * 16);
    }
}

// ---------------- QKV GEMM (mma.sync + 2-stage cp.async) + LN/quant epilogue ----------------
// grid (18, 128), 256 threads, dyn smem 67584
__global__ void __launch_bounds__(256) k_gemm1(
        const float* __restrict__ qkv_alpha,
        const float* __restrict__ nqw, const float* __restrict__ nqb,
        const float* __restrict__ nkw, const float* __restrict__ nkb){
    extern __shared__ int smw[];
    uint32_t smb = smem_u32(smw);
    int tid = threadIdx.x, lane = tid & 31, wid = tid >> 5;
    int wrBase = (wid >> 2) * 64;
    int wcBase = (wid & 3) * 32;
    int rowBase = blockIdx.y << 7, colBase = blockIdx.x << 7;
    const s8* Ag = g_xq + (size_t)rowBase * 768;
    const s8* Bg = g_wq + (size_t)colBase * 768;

    int acc[4][4][4];
#pragma unroll
    for (int mt = 0; mt < 4; mt++)
#pragma unroll
        for (int nt = 0; nt < 4; nt++)
#pragma unroll
            for (int q = 0; q < 4; q++) acc[mt][nt][q] = 0;

    gemm_stage_load(smb, 0, tid, Ag, Bg, 0);
    CPA_COMMIT();
    for (int kc = 0; kc < 6; kc++){
        if (kc < 5){
            gemm_stage_load(smb, (kc + 1) & 1, tid, Ag, Bg, (kc + 1) * 128);
            CPA_COMMIT();
            CPA_WAIT(1);
        } else {
            CPA_WAIT(0);
        }
        __syncthreads();
        const s8* Atile = (const s8*)smw + (kc & 1) * 32768;
        const s8* Btile = Atile + 16384;
        gemm_stage_compute(Atile, Btile, lane, wrBase, wcBase, acc);
        __syncthreads();
    }

    // stage C tile in smem: [128][132]
    int* Cs = smw;
#pragma unroll
    for (int mt = 0; mt < 4; mt++)
#pragma unroll
        for (int nt = 0; nt < 4; nt++){
            int r0 = wrBase + mt * 16 + (lane >> 2);
            int cl = wcBase + nt * 8 + 2 * (lane & 3);
            Cs[r0 * 132 + cl]           = acc[mt][nt][0];
            Cs[r0 * 132 + cl + 1]       = acc[mt][nt][1];
            Cs[(r0 + 8) * 132 + cl]     = acc[mt][nt][2];
            Cs[(r0 + 8) * 132 + cl + 1] = acc[mt][nt][3];
        }
    __syncthreads();

    float a_in = g_sc[0];
    for (int it = wid; it < 256; it += 8){
        int r = it >> 1, g = it & 1;
        int th = (blockIdx.x << 1) + g;
        int t  = th / 12, h = th - 12 * t;
        int row = rowBase + r;
        int b_ = row >> 9, n = row & 511;
        int d0 = lane * 2;
        int jg = th * 64;
        float al0 = qkv_alpha[jg + d0], al1 = qkv_alpha[jg + d0 + 1];
        float c0 = __fadd_rn((float)Cs[r*132 + g*64 + d0],     g_bi[jg + d0]);
        float c1 = __fadd_rn((float)Cs[r*132 + g*64 + d0 + 1], g_bi[jg + d0 + 1]);
        if (t == 2){
            float va = g_sc[3];
            float ap0 = __fdiv_rn(va, __fmul_rn(a_in, al0));
            float ap1 = __fdiv_rn(va, __fmul_rn(a_in, al1));
            float r0 = fminf(fmaxf(__fdiv_rn(c0, ap0), -4.f), 3.f);
            float r1 = fminf(fmaxf(__fdiv_rn(c1, ap1), -4.f), 3.f);
            s8* dst = g_v2t + (size_t)(b_*12 + h) * 64 * 512;
            dst[(size_t)d0 * 512 + n]       = (s8)(int)rintf(r0);
            dst[(size_t)(d0+1) * 512 + n]   = (s8)(int)rintf(r1);
        } else {
            float xs0 = __fmul_rn(c0, al0), xs1 = __fmul_rn(c1, al1);
            float ssum = warp_sum(__fadd_rn(xs0, xs1));
            float mean = __fdiv_rn(ssum, 64.0f);
            float dv0 = __fadd_rn(xs0, -mean), dv1 = __fadd_rn(xs1, -mean);
            float vs = warp_sum(__fadd_rn(__fmul_rn(dv0, dv0), __fmul_rn(dv1, dv1)));
            float stdv = __fsqrt_rn(__fdiv_rn(vs, 63.0f));
            float den = __fadd_rn(stdv, 1e-5f);
            float xh0 = __fdiv_rn(dv0, den), xh1 = __fdiv_rn(dv1, den);
            const float* w  = (t == 0) ? nqw : nkw;
            const float* bb = (t == 0) ? nqb : nkb;
            float act = (t == 0) ? g_sc[1] : g_sc[2];
            float w0 = w[d0], w1 = w[d0 + 1];
            float alp0 = __fdiv_rn(act, w0), alp1 = __fdiv_rn(act, w1);
            float bi0 = __fdiv_rn(bb[d0], w0), bi1 = __fdiv_rn(bb[d0 + 1], w1);
            float r0 = fminf(fmaxf(__fdiv_rn(__fadd_rn(xh0, bi0), alp0), -4.f), 3.f);
            float r1 = fminf(fmaxf(__fdiv_rn(__fadd_rn(xh1, bi1), alp1), -4.f), 3.f);
            s8* dst = (t == 0) ? g_q2 : g_k2;
            size_t o = ((size_t)(b_*12 + h) * 512 + n) * 64 + d0;
            dst[o]     = (s8)(int)rintf(r0);
            dst[o + 1] = (s8)(int)rintf(r1);
        }
    }
}

// ---------------- attention: 4 q-rows/thread; pipelined K loads ----------------
// grid (384, 8), 256 threads, dyn smem 113152 B
#define DP16(sacc, ar, b0, b1, b2, b3)                   \
    sacc = __dp4a((ar)[0],  (b0).x, sacc); sacc = __dp4a((ar)[1],  (b0).y, sacc); \
    sacc = __dp4a((ar)[2],  (b0).z, sacc); sacc = __dp4a((ar)[3],  (b0).w, sacc); \
    sacc = __dp4a((ar)[4],  (b1).x, sacc); sacc = __dp4a((ar)[5],  (b1).y, sacc); \
    sacc = __dp4a((ar)[6],  (b1).z, sacc); sacc = __dp4a((ar)[7],  (b1).w, sacc); \
    sacc = __dp4a((ar)[8],  (b2).x, sacc); sacc = __dp4a((ar)[9],  (b2).y, sacc); \
    sacc = __dp4a((ar)[10], (b2).z, sacc); sacc = __dp4a((ar)[11], (b2).w, sacc); \
    sacc = __dp4a((ar)[12], (b3).x, sacc); sacc = __dp4a((ar)[13], (b3).y, sacc); \
    sacc = __dp4a((ar)[14], (b3).z, sacc); sacc = __dp4a((ar)[15], (b3).w, sacc)

__global__ void __launch_bounds__(256, 2) k_attn(){
    extern __shared__ int smw[];
    int*   qs   = smw;                        // 1024
    int*   ks   = smw + 1024;                 // 8256 (staggered per 32 rows)
    int*   vTw  = smw + 9280;                 // 8448
    int*   es   = smw + 17728;                // 8448
    float* rs2  = (float*)(smw + 26176);      // 1024 floats [64][16]
    float* rsum = rs2 + 1024;                 // 64
    s8*    lut  = (s8*)(rsum + 64);           // 64 x 64 = 4096 B

    int tid = threadIdx.x;
    int bh = blockIdx.x, qt = blockIdx.y;
    size_t base = (size_t)bh * 512 * 64;

    const int4* qg = (const int4*)(g_q2 + base + (size_t)qt * 4096);
    ((int4*)qs)[tid] = qg[tid];
    const int4* kg = (const int4*)(g_k2 + base);
#pragma unroll
    for (int i = tid; i < 2048; i += 256){
        int ki = i >> 2, seg = i & 3;
        *(int4*)&ks[ki * 16 + (ki >> 5) * 4 + seg * 4] = kg[i];
    }
    const int4* vg = (const int4*)(g_v2t + base);
#pragma unroll
    for (int i = tid; i < 2048; i += 256){
        int d = i >> 5, seg = i & 31;
        ((int4*)&vTw[d * 132])[seg] = vg[i];
    }
    __syncthreads();

    int qq = tid >> 4, qr = tid & 15;     // q rows {qq+16j}, k slice [qr*32, +32)
    int areg[4][16];
#pragma unroll
    for (int j = 0; j < 4; j++)
#pragma unroll
        for (int w = 0; w < 16; w++) areg[j][w] = qs[(qq + 16*j) * 16 + w];

    float cs2 = __fmul_rn(g_sc[6], 128.0f);   // exact power-of-2 fold
    int packed[4] = {0, 0, 0, 0};
    const int* ksq = ks + qr * 516;       // qr*32 rows * 16 ints + qr*4 stagger
    int4 b0, b1, b2, b3;
    {
        const int4* kr = (const int4*)ksq;
        b0 = kr[0]; b1 = kr[1]; b2 = kr[2]; b3 = kr[3];
    }
    for (int i = 0; i < 32; i++){
        int4 n0, n1, n2, n3;
        if (i < 31){
            const int4* nx = (const int4*)(ksq + (i + 1) * 16);
            n0 = nx[0]; n1 = nx[1]; n2 = nx[2]; n3 = nx[3];
        }
#pragma unroll
        for (int j = 0; j < 4; j++){
            int s = 0;
            DP16(s, areg[j], b0, b1, b2, b3);
            float e = truncf(__fmul_rn(cs2, (float)s));
            int ei = (int)rintf(__fmul_rn(e, 0.0078125f));
            packed[j] |= (ei & 0xff) << ((i & 3) * 8);
        }
        if ((i & 3) == 3){
            int k4 = qr * 8 + (i >> 2);
#pragma unroll
            for (int j = 0; j < 4; j++){
                es[(qq + 16*j) * 132 + k4] = packed[j];
                packed[j] = 0;
            }
        }
        b0 = n0; b1 = n1; b2 = n2; b3 = n3;
    }
    __syncthreads();

    // pass A: per-(row,slice) partial sums, identical summation grouping/order
#pragma unroll
    for (int p = 0; p < 4; p++){
        int it = tid + p * 256;           // 0..1023
        int row = it >> 4, slice = it & 15;
        const int* er = es + row * 132 + slice * 8;
        float psum = 0.f;
#pragma unroll
        for (int m = 0; m < 8; m++){
            int e4 = er[m];
            psum = __fadd_rn(psum, p2i((int)(s8)(e4)));
            psum = __fadd_rn(psum, p2i((int)(s8)(e4 >> 8)));
            psum = __fadd_rn(psum, p2i((int)(s8)(e4 >> 16)));
            psum = __fadd_rn(psum, p2i((int)(s8)(e4 >> 24)));
        }
        rs2[row * 16 + slice] = psum;
    }
    __syncthreads();
    if (tid < 64){
        const float* r16 = rs2 + tid * 16;
        float s = r16[0];
#pragma unroll
        for (int j = 1; j < 16; j++) s = __fadd_rn(s, r16[j]);
        rsum[tid] = s;
    }
    __syncthreads();

    float aa = g_sc[4];
    for (int w = tid; w < 4096; w += 256){
        int row = w >> 6, j = w & 63;
        float p = p2i(j - 32);
        float su = rsum[row];
        float r = fminf(fmaxf(__fdiv_rn(__fdiv_rn(p, su), aa), 0.f), 7.f);
        lut[w] = (s8)(int)rintf(r);
    }
    __syncthreads();

    for (int w = tid; w < 8192; w += 256){
        int q2i = w >> 7, k4 = w & 127;
        int e4 = es[q2i * 132 + k4];
        const s8* lr = lut + (q2i << 6);
        int out = 0;
#pragma unroll
        for (int b = 0; b < 4; b++){
            int ei = (int)(s8)(e4 >> (b * 8));
            int j = min(max(ei + 32, 0), 63);
            out |= ((int)lr[j]) << (b * 8);
        }
        es[q2i * 132 + k4] = out;
    }
    __syncthreads();

    // AV: q rows {qq+16j}, d = qr + 16*dd (dd < 4); aw via explicit int4 loads
    int acc[4][4];
#pragma unroll
    for (int j = 0; j < 4; j++)
#pragma unroll
        for (int dd = 0; dd < 4; dd++) acc[j][dd] = 0;
#pragma unroll
    for (int c = 0; c < 8; c++){
        int aw[4][16];
#pragma unroll
        for (int j = 0; j < 4; j++){
            const int4* ar = (const int4*)&es[(qq + 16*j) * 132 + c * 16];
            int4 t0 = ar[0], t1 = ar[1], t2 = ar[2], t3 = ar[3];
            aw[j][0]=t0.x; aw[j][1]=t0.y; aw[j][2]=t0.z; aw[j][3]=t0.w;
            aw[j][4]=t1.x; aw[j][5]=t1.y; aw[j][6]=t1.z; aw[j][7]=t1.w;
            aw[j][8]=t2.x; aw[j][9]=t2.y; aw[j][10]=t2.z; aw[j][11]=t2.w;
            aw[j][12]=t3.x; aw[j][13]=t3.y; aw[j][14]=t3.z; aw[j][15]=t3.w;
        }
#pragma unroll
        for (int dd = 0; dd < 4; dd++){
            int d = qr + 16 * dd;
            const int4* vr = (const int4*)&vTw[d * 132 + c * 16];
            int4 v0 = vr[0], v1 = vr[1], v2 = vr[2], v3 = vr[3];
#pragma unroll
            for (int j = 0; j < 4; j++){
                int s = acc[j][dd];
                DP16(s, aw[j], v0, v1, v2, v3);
                acc[j][dd] = s;
            }
        }
    }
    float apx = g_sc[7];
    int b_ = bh / 12, h = bh - 12 * b_;
    int row0 = b_ * 512 + qt * 64 + qq;
#pragma unroll
    for (int j = 0; j < 4; j++){
        s8* dst = g_x1 + (size_t)(row0 + 16*j) * 768 + h * 64;
#pragma unroll
        for (int dd = 0; dd < 4; dd++){
            float r = fminf(fmaxf(__fdiv_rn((float)acc[j][dd], apx), -4.f), 3.f);
            dst[qr + 16 * dd] = (s8)(int)rintf(r);
        }
    }
}

// ---------------- projection GEMM (mma.sync + 2-stage cp.async) ----------------
// grid (6, 128), 256 threads, dyn smem 65536
__global__ void __launch_bounds__(256) k_gemm2(
        const float* __restrict__ palpha, const float* __restrict__ pbias,
        float* __restrict__ out){
    extern __shared__ int smw[];
    uint32_t smb = smem_u32(smw);
    int tid = threadIdx.x, lane = tid & 31, wid = tid >> 5;
    int wrBase = (wid >> 2) * 64;
    int wcBase = (wid & 3) * 32;
    int rowBase = blockIdx.y << 7, colBase = blockIdx.x << 7;
    const s8* Ag = g_x1 + (size_t)rowBase * 768;
    const s8* Bg = g_pw + (size_t)colBase * 768;

    int acc[4][4][4];
#pragma unroll
    for (int mt = 0; mt < 4; mt++)
#pragma unroll
        for (int nt = 0; nt < 4; nt++)
#pragma unroll
            for (int q = 0; q < 4; q++) acc[mt][nt][q] = 0;

    gemm_stage_load(smb, 0, tid, Ag, Bg, 0);
    CPA_COMMIT();
    for (int kc = 0; kc < 6; kc++){
        if (kc < 5){
            gemm_stage_load(smb, (kc + 1) & 1, tid, Ag, Bg, (kc + 1) * 128);
            CPA_COMMIT();
            CPA_WAIT(1);
        } else {
            CPA_WAIT(0);
        }
        __syncthreads();
        const s8* Atile = (const s8*)smw + (kc & 1) * 32768;
        const s8* Btile = Atile + 16384;
        gemm_stage_compute(Atile, Btile, lane, wrBase, wcBase, acc);
        __syncthreads();
    }

    float pa = g_sc[5];
#pragma unroll
    for (int mt = 0; mt < 4; mt++)
#pragma unroll
        for (int nt = 0; nt < 4; nt++){
            int r0 = rowBase + wrBase + mt * 16 + (lane >> 2);
            int c  = colBase + wcBase + nt * 8 + 2 * (lane & 3);
            float al0 = palpha[c], al1 = palpha[c + 1];
            float bi0 = pbias[c],  bi1 = pbias[c + 1];
            out[(size_t)r0 * 768 + c]
                = __fadd_rn(__fmul_rn(__fmul_rn((float)acc[mt][nt][0], al0), pa), bi0);
            out[(size_t)r0 * 768 + c + 1]
                = __fadd_rn(__fmul_rn(__fmul_rn((float)acc[mt][nt][1], al1), pa), bi1);
            out[(size_t)(r0 + 8) * 768 + c]
                = __fadd_rn(__fmul_rn(__fmul_rn((float)acc[mt][nt][2], al0), pa), bi0);
            out[(size_t)(r0 + 8) * 768 + c + 1]
                = __fadd_rn(__fmul_rn(__fmul_rn((float)acc[mt][nt][3], al1), pa), bi1);
        }
}

// ---------------- launch ----------------
extern "C" void kernel_launch(void* const* d_in, const int* in_sizes, int n_in,
                              void* d_out, int out_size){
    const float* x0          = (const float*)d_in[0];
    const float* qkv_w       = (const float*)d_in[1];
    const float* qkv_alpha   = (const float*)d_in[2];
    const float* qkv_bias    = (const float*)d_in[3];
    const float* qkv_act_al  = (const float*)d_in[4];
    const float* proj_w      = (const float*)d_in[5];
    const float* proj_alpha  = (const float*)d_in[6];
    const float* proj_bias   = (const float*)d_in[7];
    const float* proj_act_al = (const float*)d_in[8];
    const float* normq_w     = (const float*)d_in[9];
    const float* normq_b     = (const float*)d_in[10];
    const float* normk_w     = (const float*)d_in[11];
    const float* normk_b     = (const float*)d_in[12];
    const float* qact        = (const float*)d_in[13];
    const float* kact        = (const float*)d_in[14];
    const float* vact        = (const float*)d_in[15];
    const float* attnact     = (const float*)d_in[16];
    float* out = (float*)d_out;

    cudaFuncSetAttribute(k_gemm1, cudaFuncAttributeMaxDynamicSharedMemorySize, 67584);
    cudaFuncSetAttribute(k_gemm2, cudaFuncAttributeMaxDynamicSharedMemorySize, 65536);
    cudaFuncSetAttribute(k_attn,  cudaFuncAttributeMaxDynamicSharedMemorySize, 113152);

    // order: gemm1 is our 4th launch -> lands in ncu capture slot next round
    k_scalars<<<1, 256>>>(qkv_act_al, qact, kact, vact, attnact, proj_act_al,
                          qkv_bias, qkv_alpha);
    k_quant_xw<<<4800, 256>>>(x0, qkv_w, qkv_alpha);
    k_quant_pw<<<576, 256>>>(proj_w, proj_alpha);
    k_gemm1<<<dim3(18, 128), 256, 67584>>>(qkv_alpha, normq_w, normq_b, normk_w, normk_b);
    k_attn<<<dim3(384, 8), 256, 113152>>>();
    k_gemm2<<<dim3(6, 128), 256, 65536>>>(proj_alpha, proj_bias, out);
}

// round 17
// speedup vs baseline: 1.0168x; 1.0168x over previous
#include <cuda_runtime.h>
#include <cstdint>
#include <cstddef>

#define BB 32
#define NN 512
#define CC 768
#define HH 12
#define HD 64
#define MTOT (BB*NN)      // 16384
#define NC3 (3*CC)        // 2304

typedef signed char s8;

// ---------------- device scratch (allocation-free) ----------------
__device__ float g_sc[8]; // 0:a_in 1:qa 2:ka 3:va 4:aa 5:pa 6:cs1 7:apx
__device__ s8    g_xq[MTOT*CC];
__device__ s8    g_wq[NC3*CC];
__device__ float g_bi[NC3];
__device__ s8    g_q2[BB*HH*NN*HD];
__device__ s8    g_k2[BB*HH*NN*HD];
__device__ s8    g_v2t[BB*HH*HD*NN];   // [bh][d][n]
__device__ s8    g_x1[MTOT*CC];
__device__ s8    g_pw[CC*CC];

__device__ __forceinline__ float warp_sum(float v){
#pragma unroll
    for (int o = 16; o > 0; o >>= 1)
        v = __fadd_rn(v, __shfl_xor_sync(0xffffffffu, v, o));
    return v;
}

__device__ __forceinline__ s8 q_rc(float v, float a, float lo, float hi){
    float r = __fdiv_rn(v, a);
    r = fminf(fmaxf(r, lo), hi);
    return (s8)(int)rintf(r);
}

// exact 2^ei for integer ei >= -126
__device__ __forceinline__ float p2i(int ei){
    int ec = max(ei, -126);
    return __int_as_float((ec + 127) << 23);
}

__device__ __forceinline__ void mma_s8(int* d, const int* a, const int* b){
    asm volatile(
        "mma.sync.aligned.m16n8k32.row.col.s32.s8.s8.s32 "
        "{%0,%1,%2,%3}, {%4,%5,%6,%7}, {%8,%9}, {%0,%1,%2,%3};"
        : "+r"(d[0]), "+r"(d[1]), "+r"(d[2]), "+r"(d[3])
        : "r"(a[0]), "r"(a[1]), "r"(a[2]), "r"(a[3]), "r"(b[0]), "r"(b[1]));
}

__device__ __forceinline__ uint32_t smem_u32(const void* p){
    uint32_t a;
    asm("{ .reg .u64 t; cvta.to.shared.u64 t, %1; cvt.u32.u64 %0, t; }" : "=r"(a) : "l"(p));
    return a;
}
__device__ __forceinline__ void cpa16(uint32_t dst, const void* src){
    asm volatile("cp.async.ca.shared.global [%0], [%1], 16;" :: "r"(dst), "l"(src));
}
#define CPA_COMMIT() asm volatile("cp.async.commit_group;" ::: "memory")
#define CPA_WAIT(n)  asm volatile("cp.async.wait_group %0;" :: "n"(n) : "memory")

// ---------------- scalar means + integer bias ----------------
__global__ void k_scalars(const float* __restrict__ qaa, const float* __restrict__ qact,
                          const float* __restrict__ kact, const float* __restrict__ vact,
                          const float* __restrict__ aact, const float* __restrict__ paa,
                          const float* __restrict__ qkv_bias, const float* __restrict__ qkv_alpha){
    int tid = threadIdx.x;
    if (tid < 32){
        int lane = tid;
        float s = 0.f;
        for (int i = lane; i < 768; i += 32) s = __fadd_rn(s, qaa[i]);
        float a_in = __fdiv_rn(warp_sum(s), 768.0f);
        s = 0.f;
        for (int i = lane; i < 768; i += 32) s = __fadd_rn(s, paa[i]);
        float pa = __fdiv_rn(warp_sum(s), 768.0f);
        float t;
        t = (lane < 12) ? qact[lane] : 0.f; float qa = __fdiv_rn(warp_sum(t), 12.0f);
        t = (lane < 12) ? kact[lane] : 0.f; float ka = __fdiv_rn(warp_sum(t), 12.0f);
        t = (lane < 12) ? vact[lane] : 0.f; float va = __fdiv_rn(warp_sum(t), 12.0f);
        t = (lane < 12) ? aact[lane] : 0.f; float aa = __fdiv_rn(warp_sum(t), 12.0f);
        if (lane == 0){
            g_sc[0] = a_in; g_sc[1] = qa; g_sc[2] = ka; g_sc[3] = va; g_sc[4] = aa; g_sc[5] = pa;
            float sm = __fmul_rn(__fmul_rn(0.125f, qa), ka);
            g_sc[6] = __fmul_rn(1.4426950408889634f, sm);
            g_sc[7] = __fdiv_rn(pa, __fmul_rn(aa, va));
        }
    }
    __syncthreads();
    float a_in = g_sc[0];
    for (int j = tid; j < NC3; j += 256)
        g_bi[j] = truncf(__fdiv_rn(__fdiv_rn(qkv_bias[j], a_in), qkv_alpha[j]));
}

// ---------------- fused quantization: x (0..3071), qkv_w (3072..4799), proj_w (4800..5375) ----------------
__global__ void k_quant_all(const float* __restrict__ x, const float* __restrict__ w,
                            const float* __restrict__ al,
                            const float* __restrict__ pw, const float* __restrict__ pal){
    if (blockIdx.x < 3072){
        float a = g_sc[0];
        int base = blockIdx.x * 1024 + threadIdx.x;
        float4 v[4];
#pragma unroll
        for (int p = 0; p < 4; p++) v[p] = ((const float4*)x)[base + p * 256];
#pragma unroll
        for (int p = 0; p < 4; p++){
            char4 c;
            c.x = q_rc(v[p].x, a, -8.f, 7.f); c.y = q_rc(v[p].y, a, -8.f, 7.f);
            c.z = q_rc(v[p].z, a, -8.f, 7.f); c.w = q_rc(v[p].w, a, -8.f, 7.f);
            ((char4*)g_xq)[base + p * 256] = c;
        }
    } else if (blockIdx.x < 4800){
        int idx = (blockIdx.x - 3072) * 256 + threadIdx.x;
        int row = idx / 192;
        float a = al[row];
        float4 v = ((const float4*)w)[idx];
        char4 c;
        c.x = q_rc(v.x, a, -8.f, 7.f); c.y = q_rc(v.y, a, -8.f, 7.f);
        c.z = q_rc(v.z, a, -8.f, 7.f); c.w = q_rc(v.w, a, -8.f, 7.f);
        ((char4*)g_wq)[idx] = c;
    } else {
        int idx = (blockIdx.x - 4800) * 256 + threadIdx.x;
        int row = idx / 192;
        float a = pal[row];
        float4 v = ((const float4*)pw)[idx];
        char4 c;
        c.x = q_rc(v.x, a, -8.f, 7.f); c.y = q_rc(v.y, a, -8.f, 7.f);
        c.z = q_rc(v.z, a, -8.f, 7.f); c.w = q_rc(v.w, a, -8.f, 7.f);
        ((char4*)g_pw)[idx] = c;
    }
}

// ---------------- GEMM compute tile (gemm1, 128x128) ----------------
__device__ __forceinline__ void gemm_stage_compute(
        const s8* Atile, const s8* Btile, int lane, int wrBase, int wcBase,
        int acc[4][4][4]){
#pragma unroll
    for (int s = 0; s < 4; s++){
        int c4 = (lane & 3) * 4;
        int afr[4][4];
#pragma unroll
        for (int mt = 0; mt < 4; mt++){
            int r0 = wrBase + mt * 16 + (lane >> 2);
            int r1 = r0 + 8;
            afr[mt][0] = *(const int*)(Atile + r0*128 + (((2*s  ) ^ (r0 & 7)) * 16) + c4);
            afr[mt][1] = *(const int*)(Atile + r1*128 + (((2*s  ) ^ (r1 & 7)) * 16) + c4);
            afr[mt][2] = *(const int*)(Atile + r0*128 + (((2*s+1) ^ (r0 & 7)) * 16) + c4);
            afr[mt][3] = *(const int*)(Atile + r1*128 + (((2*s+1) ^ (r1 & 7)) * 16) + c4);
        }
        int bfr[4][2];
#pragma unroll
        for (int nt = 0; nt < 4; nt++){
            int c0 = wcBase + nt * 8 + (lane >> 2);
            bfr[nt][0] = *(const int*)(Btile + c0*128 + (((2*s  ) ^ (c0 & 7)) * 16) + c4);
            bfr[nt][1] = *(const int*)(Btile + c0*128 + (((2*s+1) ^ (c0 & 7)) * 16) + c4);
        }
#pragma unroll
        for (int mt = 0; mt < 4; mt++)
#pragma unroll
            for (int nt = 0; nt < 4; nt++)
                mma_s8(acc[mt][nt], afr[mt], bfr[nt]);
    }
}

__device__ __forceinline__ void gemm_stage_load(
        uint32_t smb, int stage, int tid,
        const s8* __restrict__ Ag, const s8* __restrict__ Bg, int kt){
    uint32_t sA = smb + stage * 32768;
    uint32_t sB = sA + 16384;
#pragma unroll
    for (int p = 0; p < 4; p++){
        int idx = tid + p * 256;
        int r = idx >> 3, seg = idx & 7;
        uint32_t off = r * 128 + ((seg ^ (r & 7)) * 16);
        cpa16(sA + off, Ag + (size_t)r * 768 + kt + seg * 16);
        cpa16(sB + off, Bg + (size_t)r * 768 + kt + seg * 16);
    }
}

// ---------------- QKV GEMM (mma.sync + 2-stage cp.async) + LN/quant epilogue ----------------
// grid (18, 128), 256 threads, dyn smem 67584
__global__ void __launch_bounds__(256) k_gemm1(
        const float* __restrict__ qkv_alpha,
        const float* __restrict__ nqw, const float* __restrict__ nqb,
        const float* __restrict__ nkw, const float* __restrict__ nkb){
    extern __shared__ int smw[];
    uint32_t smb = smem_u32(smw);
    int tid = threadIdx.x, lane = tid & 31, wid = tid >> 5;
    int wrBase = (wid >> 2) * 64;
    int wcBase = (wid & 3) * 32;
    int rowBase = blockIdx.y << 7, colBase = blockIdx.x << 7;
    const s8* Ag = g_xq + (size_t)rowBase * 768;
    const s8* Bg = g_wq + (size_t)colBase * 768;

    int acc[4][4][4];
#pragma unroll
    for (int mt = 0; mt < 4; mt++)
#pragma unroll
        for (int nt = 0; nt < 4; nt++)
#pragma unroll
            for (int q = 0; q < 4; q++) acc[mt][nt][q] = 0;

    gemm_stage_load(smb, 0, tid, Ag, Bg, 0);
    CPA_COMMIT();
    for (int kc = 0; kc < 6; kc++){
        if (kc < 5){
            gemm_stage_load(smb, (kc + 1) & 1, tid, Ag, Bg, (kc + 1) * 128);
            CPA_COMMIT();
            CPA_WAIT(1);
        } else {
            CPA_WAIT(0);
        }
        __syncthreads();
        const s8* Atile = (const s8*)smw + (kc & 1) * 32768;
        const s8* Btile = Atile + 16384;
        gemm_stage_compute(Atile, Btile, lane, wrBase, wcBase, acc);
        __syncthreads();
    }

    // stage C tile in smem: [128][132]
    int* Cs = smw;
#pragma unroll
    for (int mt = 0; mt < 4; mt++)
#pragma unroll
        for (int nt = 0; nt < 4; nt++){
            int r0 = wrBase + mt * 16 + (lane >> 2);
            int cl = wcBase + nt * 8 + 2 * (lane & 3);
            Cs[r0 * 132 + cl]           = acc[mt][nt][0];
            Cs[r0 * 132 + cl + 1]       = acc[mt][nt][1];
            Cs[(r0 + 8) * 132 + cl]     = acc[mt][nt][2];
            Cs[(r0 + 8) * 132 + cl + 1] = acc[mt][nt][3];
        }
    __syncthreads();

    float a_in = g_sc[0];
    for (int it = wid; it < 256; it += 8){
        int r = it >> 1, g = it & 1;
        int th = (blockIdx.x << 1) + g;
        int t  = th / 12, h = th - 12 * t;
        int row = rowBase + r;
        int b_ = row >> 9, n = row & 511;
        int d0 = lane * 2;
        int jg = th * 64;
        float al0 = qkv_alpha[jg + d0], al1 = qkv_alpha[jg + d0 + 1];
        float c0 = __fadd_rn((float)Cs[r*132 + g*64 + d0],     g_bi[jg + d0]);
        float c1 = __fadd_rn((float)Cs[r*132 + g*64 + d0 + 1], g_bi[jg + d0 + 1]);
        if (t == 2){
            float va = g_sc[3];
            float ap0 = __fdiv_rn(va, __fmul_rn(a_in, al0));
            float ap1 = __fdiv_rn(va, __fmul_rn(a_in, al1));
            float r0 = fminf(fmaxf(__fdiv_rn(c0, ap0), -4.f), 3.f);
            float r1 = fminf(fmaxf(__fdiv_rn(c1, ap1), -4.f), 3.f);
            s8* dst = g_v2t + (size_t)(b_*12 + h) * 64 * 512;
            dst[(size_t)d0 * 512 + n]       = (s8)(int)rintf(r0);
            dst[(size_t)(d0+1) * 512 + n]   = (s8)(int)rintf(r1);
        } else {
            float xs0 = __fmul_rn(c0, al0), xs1 = __fmul_rn(c1, al1);
            float ssum = warp_sum(__fadd_rn(xs0, xs1));
            float mean = __fdiv_rn(ssum, 64.0f);
            float dv0 = __fadd_rn(xs0, -mean), dv1 = __fadd_rn(xs1, -mean);
            float vs = warp_sum(__fadd_rn(__fmul_rn(dv0, dv0), __fmul_rn(dv1, dv1)));
            float stdv = __fsqrt_rn(__fdiv_rn(vs, 63.0f));
            float den = __fadd_rn(stdv, 1e-5f);
            float xh0 = __fdiv_rn(dv0, den), xh1 = __fdiv_rn(dv1, den);
            const float* w  = (t == 0) ? nqw : nkw;
            const float* bb = (t == 0) ? nqb : nkb;
            float act = (t == 0) ? g_sc[1] : g_sc[2];
            float w0 = w[d0], w1 = w[d0 + 1];
            float alp0 = __fdiv_rn(act, w0), alp1 = __fdiv_rn(act, w1);
            float bi0 = __fdiv_rn(bb[d0], w0), bi1 = __fdiv_rn(bb[d0 + 1], w1);
            float r0 = fminf(fmaxf(__fdiv_rn(__fadd_rn(xh0, bi0), alp0), -4.f), 3.f);
            float r1 = fminf(fmaxf(__fdiv_rn(__fadd_rn(xh1, bi1), alp1), -4.f), 3.f);
            s8* dst = (t == 0) ? g_q2 : g_k2;
            size_t o = ((size_t)(b_*12 + h) * 512 + n) * 64 + d0;
            dst[o]     = (s8)(int)rintf(r0);
            dst[o + 1] = (s8)(int)rintf(r1);
        }
    }
}

// ---------------- attention (R16 version) ----------------
// grid (384, 8), 256 threads, dyn smem 113152 B
#define DP16(sacc, ar, b0, b1, b2, b3)                   \
    sacc = __dp4a((ar)[0],  (b0).x, sacc); sacc = __dp4a((ar)[1],  (b0).y, sacc); \
    sacc = __dp4a((ar)[2],  (b0).z, sacc); sacc = __dp4a((ar)[3],  (b0).w, sacc); \
    sacc = __dp4a((ar)[4],  (b1).x, sacc); sacc = __dp4a((ar)[5],  (b1).y, sacc); \
    sacc = __dp4a((ar)[6],  (b1).z, sacc); sacc = __dp4a((ar)[7],  (b1).w, sacc); \
    sacc = __dp4a((ar)[8],  (b2).x, sacc); sacc = __dp4a((ar)[9],  (b2).y, sacc); \
    sacc = __dp4a((ar)[10], (b2).z, sacc); sacc = __dp4a((ar)[11], (b2).w, sacc); \
    sacc = __dp4a((ar)[12], (b3).x, sacc); sacc = __dp4a((ar)[13], (b3).y, sacc); \
    sacc = __dp4a((ar)[14], (b3).z, sacc); sacc = __dp4a((ar)[15], (b3).w, sacc)

__global__ void __launch_bounds__(256, 2) k_attn(){
    extern __shared__ int smw[];
    int*   qs   = smw;                        // 1024
    int*   ks   = smw + 1024;                 // 8256 (staggered per 32 rows)
    int*   vTw  = smw + 9280;                 // 8448
    int*   es   = smw + 17728;                // 8448
    float* rs2  = (float*)(smw + 26176);      // 1024 floats [64][16]
    float* rsum = rs2 + 1024;                 // 64
    s8*    lut  = (s8*)(rsum + 64);           // 64 x 64 = 4096 B

    int tid = threadIdx.x;
    int bh = blockIdx.x, qt = blockIdx.y;
    size_t base = (size_t)bh * 512 * 64;

    const int4* qg = (const int4*)(g_q2 + base + (size_t)qt * 4096);
    ((int4*)qs)[tid] = qg[tid];
    const int4* kg = (const int4*)(g_k2 + base);
#pragma unroll
    for (int i = tid; i < 2048; i += 256){
        int ki = i >> 2, seg = i & 3;
        *(int4*)&ks[ki * 16 + (ki >> 5) * 4 + seg * 4] = kg[i];
    }
    const int4* vg = (const int4*)(g_v2t + base);
#pragma unroll
    for (int i = tid; i < 2048; i += 256){
        int d = i >> 5, seg = i & 31;
        ((int4*)&vTw[d * 132])[seg] = vg[i];
    }
    __syncthreads();

    int qq = tid >> 4, qr = tid & 15;
    int areg[4][16];
#pragma unroll
    for (int j = 0; j < 4; j++)
#pragma unroll
        for (int w = 0; w < 16; w++) areg[j][w] = qs[(qq + 16*j) * 16 + w];

    float cs2 = __fmul_rn(g_sc[6], 128.0f);
    int packed[4] = {0, 0, 0, 0};
    const int* ksq = ks + qr * 516;
    int4 b0, b1, b2, b3;
    {
        const int4* kr = (const int4*)ksq;
        b0 = kr[0]; b1 = kr[1]; b2 = kr[2]; b3 = kr[3];
    }
    for (int i = 0; i < 32; i++){
        int4 n0, n1, n2, n3;
        if (i < 31){
            const int4* nx = (const int4*)(ksq + (i + 1) * 16);
            n0 = nx[0]; n1 = nx[1]; n2 = nx[2]; n3 = nx[3];
        }
#pragma unroll
        for (int j = 0; j < 4; j++){
            int s = 0;
            DP16(s, areg[j], b0, b1, b2, b3);
            float e = truncf(__fmul_rn(cs2, (float)s));
            int ei = (int)rintf(__fmul_rn(e, 0.0078125f));
            packed[j] |= (ei & 0xff) << ((i & 3) * 8);
        }
        if ((i & 3) == 3){
            int k4 = qr * 8 + (i >> 2);
#pragma unroll
            for (int j = 0; j < 4; j++){
                es[(qq + 16*j) * 132 + k4] = packed[j];
                packed[j] = 0;
            }
        }
        b0 = n0; b1 = n1; b2 = n2; b3 = n3;
    }
    __syncthreads();

#pragma unroll
    for (int p = 0; p < 4; p++){
        int it = tid + p * 256;
        int row = it >> 4, slice = it & 15;
        const int* er = es + row * 132 + slice * 8;
        float psum = 0.f;
#pragma unroll
        for (int m = 0; m < 8; m++){
            int e4 = er[m];
            psum = __fadd_rn(psum, p2i((int)(s8)(e4)));
            psum = __fadd_rn(psum, p2i((int)(s8)(e4 >> 8)));
            psum = __fadd_rn(psum, p2i((int)(s8)(e4 >> 16)));
            psum = __fadd_rn(psum, p2i((int)(s8)(e4 >> 24)));
        }
        rs2[row * 16 + slice] = psum;
    }
    __syncthreads();
    if (tid < 64){
        const float* r16 = rs2 + tid * 16;
        float s = r16[0];
#pragma unroll
        for (int j = 1; j < 16; j++) s = __fadd_rn(s, r16[j]);
        rsum[tid] = s;
    }
    __syncthreads();

    float aa = g_sc[4];
    for (int w = tid; w < 4096; w += 256){
        int row = w >> 6, j = w & 63;
        float p = p2i(j - 32);
        float su = rsum[row];
        float r = fminf(fmaxf(__fdiv_rn(__fdiv_rn(p, su), aa), 0.f), 7.f);
        lut[w] = (s8)(int)rintf(r);
    }
    __syncthreads();

    for (int w = tid; w < 8192; w += 256){
        int q2i = w >> 7, k4 = w & 127;
        int e4 = es[q2i * 132 + k4];
        const s8* lr = lut + (q2i << 6);
        int out = 0;
#pragma unroll
        for (int b = 0; b < 4; b++){
            int ei = (int)(s8)(e4 >> (b * 8));
            int j = min(max(ei + 32, 0), 63);
            out |= ((int)lr[j]) << (b * 8);
        }
        es[q2i * 132 + k4] = out;
    }
    __syncthreads();

    int acc[4][4];
#pragma unroll
    for (int j = 0; j < 4; j++)
#pragma unroll
        for (int dd = 0; dd < 4; dd++) acc[j][dd] = 0;
#pragma unroll
    for (int c = 0; c < 8; c++){
        int aw[4][16];
#pragma unroll
        for (int j = 0; j < 4; j++){
            const int4* ar = (const int4*)&es[(qq + 16*j) * 132 + c * 16];
            int4 t0 = ar[0], t1 = ar[1], t2 = ar[2], t3 = ar[3];
            aw[j][0]=t0.x; aw[j][1]=t0.y; aw[j][2]=t0.z; aw[j][3]=t0.w;
            aw[j][4]=t1.x; aw[j][5]=t1.y; aw[j][6]=t1.z; aw[j][7]=t1.w;
            aw[j][8]=t2.x; aw[j][9]=t2.y; aw[j][10]=t2.z; aw[j][11]=t2.w;
            aw[j][12]=t3.x; aw[j][13]=t3.y; aw[j][14]=t3.z; aw[j][15]=t3.w;
        }
#pragma unroll
        for (int dd = 0; dd < 4; dd++){
            int d = qr + 16 * dd;
            const int4* vr = (const int4*)&vTw[d * 132 + c * 16];
            int4 v0 = vr[0], v1 = vr[1], v2 = vr[2], v3 = vr[3];
#pragma unroll
            for (int j = 0; j < 4; j++){
                int s = acc[j][dd];
                DP16(s, aw[j], v0, v1, v2, v3);
                acc[j][dd] = s;
            }
        }
    }
    float apx = g_sc[7];
    int b_ = bh / 12, h = bh - 12 * b_;
    int row0 = b_ * 512 + qt * 64 + qq;
#pragma unroll
    for (int j = 0; j < 4; j++){
        s8* dst = g_x1 + (size_t)(row0 + 16*j) * 768 + h * 64;
#pragma unroll
        for (int dd = 0; dd < 4; dd++){
            float r = fminf(fmaxf(__fdiv_rn((float)acc[j][dd], apx), -4.f), 3.f);
            dst[qr + 16 * dd] = (s8)(int)rintf(r);
        }
    }
}

// ---------------- projection GEMM: 128x64 tiles (wave-quantization fix) ----------------
// grid (12, 128), 256 threads, dyn smem 49152 (2 stages x (A 16384 + B 8192))
__global__ void __launch_bounds__(256) k_gemm2(
        const float* __restrict__ palpha, const float* __restrict__ pbias,
        float* __restrict__ out){
    extern __shared__ int smw[];
    uint32_t smb = smem_u32(smw);
    int tid = threadIdx.x, lane = tid & 31, wid = tid >> 5;
    int wrBase = (wid >> 2) * 64;     // rows 0-63 / 64-127
    int wcBase = (wid & 3) * 16;      // cols 0/16/32/48
    int rowBase = blockIdx.y << 7, colBase = blockIdx.x << 6;
    const s8* Ag = g_x1 + (size_t)rowBase * 768;
    const s8* Bg = g_pw + (size_t)colBase * 768;

    int acc[4][2][4];
#pragma unroll
    for (int mt = 0; mt < 4; mt++)
#pragma unroll
        for (int nt = 0; nt < 2; nt++)
#pragma unroll
            for (int q = 0; q < 4; q++) acc[mt][nt][q] = 0;

    // stage layout: A at smb + stage*24576 (16384 B), B at +16384 (8192 B)
#define G2_LOAD(stage, kt) do {                                              \
        uint32_t sA = smb + (stage) * 24576;                                 \
        uint32_t sB = sA + 16384;                                            \
        _Pragma("unroll")                                                    \
        for (int p = 0; p < 4; p++){                                         \
            int idx = tid + p * 256;                                         \
            int r = idx >> 3, seg = idx & 7;                                 \
            uint32_t off = r * 128 + ((seg ^ (r & 7)) * 16);                 \
            cpa16(sA + off, Ag + (size_t)r * 768 + (kt) + seg * 16);         \
        }                                                                    \
        _Pragma("unroll")                                                    \
        for (int p = 0; p < 2; p++){                                         \
            int idx = tid + p * 256;                                         \
            int r = idx >> 3, seg = idx & 7;                                 \
            uint32_t off = r * 128 + ((seg ^ (r & 7)) * 16);                 \
            cpa16(sB + off, Bg + (size_t)r * 768 + (kt) + seg * 16);         \
        }                                                                    \
    } while (0)

    G2_LOAD(0, 0);
    CPA_COMMIT();
    for (int kc = 0; kc < 6; kc++){
        if (kc < 5){
            G2_LOAD((kc + 1) & 1, (kc + 1) * 128);
            CPA_COMMIT();
            CPA_WAIT(1);
        } else {
            CPA_WAIT(0);
        }
        __syncthreads();
        const s8* Atile = (const s8*)smw + (kc & 1) * 24576;
        const s8* Btile = Atile + 16384;
#pragma unroll
        for (int s = 0; s < 4; s++){
            int c4 = (lane & 3) * 4;
            int afr[4][4];
#pragma unroll
            for (int mt = 0; mt < 4; mt++){
                int r0 = wrBase + mt * 16 + (lane >> 2);
                int r1 = r0 + 8;
                afr[mt][0] = *(const int*)(Atile + r0*128 + (((2*s  ) ^ (r0 & 7)) * 16) + c4);
                afr[mt][1] = *(const int*)(Atile + r1*128 + (((2*s  ) ^ (r1 & 7)) * 16) + c4);
                afr[mt][2] = *(const int*)(Atile + r0*128 + (((2*s+1) ^ (r0 & 7)) * 16) + c4);
                afr[mt][3] = *(const int*)(Atile + r1*128 + (((2*s+1) ^ (r1 & 7)) * 16) + c4);
            }
            int bfr[2][2];
#pragma unroll
            for (int nt = 0; nt < 2; nt++){
                int c0 = wcBase + nt * 8 + (lane >> 2);
                bfr[nt][0] = *(const int*)(Btile + c0*128 + (((2*s  ) ^ (c0 & 7)) * 16) + c4);
                bfr[nt][1] = *(const int*)(Btile + c0*128 + (((2*s+1) ^ (c0 & 7)) * 16) + c4);
            }
#pragma unroll
            for (int mt = 0; mt < 4; mt++)
#pragma unroll
                for (int nt = 0; nt < 2; nt++)
                    mma_s8(acc[mt][nt], afr[mt], bfr[nt]);
        }
        __syncthreads();
    }
#undef G2_LOAD

    float pa = g_sc[5];
#pragma unroll
    for (int mt = 0; mt < 4; mt++)
#pragma unroll
        for (int nt = 0; nt < 2; nt++){
            int r0 = rowBase + wrBase + mt * 16 + (lane >> 2);
            int c  = colBase + wcBase + nt * 8 + 2 * (lane & 3);
            float al0 = palpha[c], al1 = palpha[c + 1];
            float bi0 = pbias[c],  bi1 = pbias[c + 1];
            out[(size_t)r0 * 768 + c]
                = __fadd_rn(__fmul_rn(__fmul_rn((float)acc[mt][nt][0], al0), pa), bi0);
            out[(size_t)r0 * 768 + c + 1]
                = __fadd_rn(__fmul_rn(__fmul_rn((float)acc[mt][nt][1], al1), pa), bi1);
            out[(size_t)(r0 + 8) * 768 + c]
                = __fadd_rn(__fmul_rn(__fmul_rn((float)acc[mt][nt][2], al0), pa), bi0);
            out[(size_t)(r0 + 8) * 768 + c + 1]
                = __fadd_rn(__fmul_rn(__fmul_rn((float)acc[mt][nt][3], al1), pa), bi1);
        }
}

// ---------------- launch ----------------
extern "C" void kernel_launch(void* const* d_in, const int* in_sizes, int n_in,
                              void* d_out, int out_size){
    const float* x0          = (const float*)d_in[0];
    const float* qkv_w       = (const float*)d_in[1];
    const float* qkv_alpha   = (const float*)d_in[2];
    const float* qkv_bias    = (const float*)d_in[3];
    const float* qkv_act_al  = (const float*)d_in[4];
    const float* proj_w      = (const float*)d_in[5];
    const float* proj_alpha  = (const float*)d_in[6];
    const float* proj_bias   = (const float*)d_in[7];
    const float* proj_act_al = (const float*)d_in[8];
    const float* normq_w     = (const float*)d_in[9];
    const float* normq_b     = (const float*)d_in[10];
    const float* normk_w     = (const float*)d_in[11];
    const float* normk_b     = (const float*)d_in[12];
    const float* qact        = (const float*)d_in[13];
    const float* kact        = (const float*)d_in[14];
    const float* vact        = (const float*)d_in[15];
    const float* attnact     = (const float*)d_in[16];
    float* out = (float*)d_out;

    cudaFuncSetAttribute(k_gemm1, cudaFuncAttributeMaxDynamicSharedMemorySize, 67584);
    cudaFuncSetAttribute(k_gemm2, cudaFuncAttributeMaxDynamicSharedMemorySize, 49152);
    cudaFuncSetAttribute(k_attn,  cudaFuncAttributeMaxDynamicSharedMemorySize, 113152);

    // attn is launch #4 -> lands in ncu capture slot
    k_scalars<<<1, 256>>>(qkv_act_al, qact, kact, vact, attnact, proj_act_al,
                          qkv_bias, qkv_alpha);
    k_quant_all<<<5376, 256>>>(x0, qkv_w, qkv_alpha, proj_w, proj_alpha);
    k_gemm1<<<dim3(18, 128), 256, 67584>>>(qkv_alpha, normq_w, normq_b, normk_w, normk_b);
    k_attn<<<dim3(384, 8), 256, 113152>>>();
    k_gemm2<<<dim3(12, 128), 256, 49152>>>(proj_alpha, proj_bias, out);
}